// round 8
// baseline (speedup 1.0000x reference)
#include <cuda_runtime.h>
#include <math.h>

#define N_NODES 100000
#define N_EDGES 800000
#define NG 64
#define HID 64
#define EMB 128

typedef unsigned long long u64;

// packed f32x2 helpers (sm_100+: fma.rn.f32x2)
__device__ __forceinline__ u64 pk2(float lo, float hi) {
    u64 r; asm("mov.b64 %0, {%1, %2};" : "=l"(r) : "f"(lo), "f"(hi)); return r;
}
__device__ __forceinline__ void upk2(u64 v, float& lo, float& hi) {
    asm("mov.b64 {%0, %1}, %2;" : "=f"(lo), "=f"(hi) : "l"(v));
}
#define FMA2(d, a, b, c) asm("fma.rn.f32x2 %0, %1, %2, %3;" : "=l"(d) : "l"(a), "l"(b), "l"(c))

// ---------------- device scratch (static allocation only) ----------------
__device__ float g_bufA[N_NODES * HID];   // hop1
__device__ float g_bufB[N_NODES * HID];   // hop2
__device__ float g_bufC[N_NODES * HID];   // hop3
__device__ float g_bufD[N_NODES * HID];   // layer output
__device__ float g_dn  [N_NODES];
__device__ int   g_deg [N_NODES];
__device__ int   g_fill[N_NODES];
__device__ int   g_rowptr[N_NODES + 1];
__device__ int   g_csr[N_EDGES];
__device__ float g_gsum[NG * HID];
__device__ int   g_gcnt[NG];

__device__ __forceinline__ float* buf_sel(int s) {
    return (s == 0) ? g_bufA : (s == 1) ? g_bufB : (s == 2) ? g_bufC : g_bufD;
}

// ---------------- init / CSR build ----------------
__global__ void k_init() {
    int i = blockIdx.x * blockDim.x + threadIdx.x;
    if (i < N_NODES) { g_deg[i] = 0; g_fill[i] = 0; }
    if (i < NG * HID) g_gsum[i] = 0.f;
    if (i < NG)       g_gcnt[i] = 0;
}

__global__ void k_deg(const int* __restrict__ dst) {
    int e = blockIdx.x * blockDim.x + threadIdx.x;
    if (e < N_EDGES) atomicAdd(&g_deg[dst[e]], 1);
}

// single-block scan (1024 threads) -> rowptr, dn
__global__ void k_scan() {
    __shared__ int sa[1024], sb[1024];
    int t = threadIdx.x;
    const int CH = (N_NODES + 1023) / 1024;   // 98
    int base = t * CH;
    int local = 0;
    for (int i = 0; i < CH; i++) {
        int idx = base + i;
        if (idx < N_NODES) local += g_deg[idx];
    }
    sa[t] = local;
    __syncthreads();
    int* cur = sa; int* nxt = sb;
    for (int off = 1; off < 1024; off <<= 1) {
        int v = cur[t] + ((t >= off) ? cur[t - off] : 0);
        nxt[t] = v;
        __syncthreads();
        int* tmp = cur; cur = nxt; nxt = tmp;
    }
    int excl = cur[t] - local;
    int run = excl;
    for (int i = 0; i < CH; i++) {
        int idx = base + i;
        if (idx < N_NODES) {
            g_rowptr[idx] = run;
            int d = g_deg[idx];
            run += d;
            g_dn[idx] = rsqrtf((float)(d > 1 ? d : 1));
        }
    }
    if (t == 1023) g_rowptr[N_NODES] = run;   // == N_EDGES
}

__global__ void k_fill(const int* __restrict__ src, const int* __restrict__ dst) {
    int e = blockIdx.x * blockDim.x + threadIdx.x;
    if (e < N_EDGES) {
        int d = dst[e];
        int pos = g_rowptr[d] + atomicAdd(&g_fill[d], 1);
        g_csr[pos] = src[e];
    }
}

// ---------------- SpMM: xout[r] = dn[r] * sum_{s in N_in(r)} dn[s]*xin[s] ----
// warp per row; half-warps process 2 edges per iter (float4/lane), unroll x2.
__global__ void __launch_bounds__(256) k_spmm(const float* __restrict__ xin_ext,
                                              int in_sel, int out_sel) {
    const float* xin = (in_sel < 0) ? xin_ext : buf_sel(in_sel);
    float* xout = buf_sel(out_sel);
    int w = (blockIdx.x * blockDim.x + threadIdx.x) >> 5;
    if (w >= N_NODES) return;
    int lane = threadIdx.x & 31;
    int half = lane >> 4;          // 0 or 1: which edge of the pair
    int q    = lane & 15;          // 16 lanes cover 64 floats as float4
    int e0 = g_rowptr[w], e1 = g_rowptr[w + 1];

    float4 acc0 = make_float4(0.f, 0.f, 0.f, 0.f);
    float4 acc1 = make_float4(0.f, 0.f, 0.f, 0.f);
    int e = e0;
    for (; e + 4 <= e1; e += 4) {
        int sA = g_csr[e + half];
        int sB = g_csr[e + 2 + half];
        float wA = g_dn[sA], wB = g_dn[sB];
        float4 vA = *(const float4*)(xin + (size_t)sA * HID + q * 4);
        float4 vB = *(const float4*)(xin + (size_t)sB * HID + q * 4);
        acc0.x = fmaf(vA.x, wA, acc0.x); acc0.y = fmaf(vA.y, wA, acc0.y);
        acc0.z = fmaf(vA.z, wA, acc0.z); acc0.w = fmaf(vA.w, wA, acc0.w);
        acc1.x = fmaf(vB.x, wB, acc1.x); acc1.y = fmaf(vB.y, wB, acc1.y);
        acc1.z = fmaf(vB.z, wB, acc1.z); acc1.w = fmaf(vB.w, wB, acc1.w);
    }
    if (e + 2 <= e1) {
        int s = g_csr[e + half];
        float wt = g_dn[s];
        float4 v = *(const float4*)(xin + (size_t)s * HID + q * 4);
        acc0.x = fmaf(v.x, wt, acc0.x); acc0.y = fmaf(v.y, wt, acc0.y);
        acc0.z = fmaf(v.z, wt, acc0.z); acc0.w = fmaf(v.w, wt, acc0.w);
        e += 2;
    }
    if (e < e1 && half == 0) {     // odd tail: only even half-warp takes it
        int s = g_csr[e];
        float wt = g_dn[s];
        float4 v = *(const float4*)(xin + (size_t)s * HID + q * 4);
        acc0.x = fmaf(v.x, wt, acc0.x); acc0.y = fmaf(v.y, wt, acc0.y);
        acc0.z = fmaf(v.z, wt, acc0.z); acc0.w = fmaf(v.w, wt, acc0.w);
    }
    acc0.x += acc1.x; acc0.y += acc1.y; acc0.z += acc1.z; acc0.w += acc1.w;
    // fold odd-half accumulators into even half (same q)
    acc0.x += __shfl_xor_sync(0xffffffffu, acc0.x, 16);
    acc0.y += __shfl_xor_sync(0xffffffffu, acc0.y, 16);
    acc0.z += __shfl_xor_sync(0xffffffffu, acc0.z, 16);
    acc0.w += __shfl_xor_sync(0xffffffffu, acc0.w, 16);
    if (half == 0) {
        float wd = g_dn[w];
        float4 o;
        o.x = acc0.x * wd; o.y = acc0.y * wd; o.z = acc0.z * wd; o.w = acc0.w * wd;
        *(float4*)(xout + (size_t)w * HID + q * 4) = o;
    }
}

// ---------------- fused layer GEMM (f32x2):
//   D = relu( in@W0c + hop1@W1c + hop2@W2c + hop3@W3c + b )
// W is [(4*64) x 64] row-major; sources: {in, bufA, bufB, bufC}.
// block 128 threads, tile 64x64, micro 8x4, acc packed over row pairs.
__global__ void __launch_bounds__(128) k_gemm4(const float* __restrict__ in_ext, int in_sel,
                                               const float* __restrict__ W,
                                               const float* __restrict__ bias,
                                               int out_sel) {
    __shared__ float xs[64 * 66];   // TRANSPOSED: xs[k*66 + r] = A[rowBase+r][k]
    __shared__ float ws[64 * 64];   // ws[k*64 + c] = W[k][c]
    int t = threadIdx.x;            // 0..127
    int rowBase = blockIdx.x * 64;

    int r0 = (t >> 4) * 8;     // 0..56 (even)
    int c0 = (t & 15) * 4;     // 0..60
    u64 acc2[4][4];            // [rowpair j: rows r0+2j, r0+2j+1][col c0+c]
#pragma unroll
    for (int j = 0; j < 4; j++)
#pragma unroll
        for (int c = 0; c < 4; c++) acc2[j][c] = 0ull;   // == {0.f, 0.f}

    const float* in0 = (in_sel < 0) ? in_ext : buf_sel(in_sel);

    for (int s = 0; s < 4; ++s) {
        const float* A = (s == 0) ? in0 : buf_sel(s - 1);   // A,B,C for s=1,2,3
        const float* Wc = W + s * 64 * 64;

        // load W chunk row-major (1024 float4; 128 threads x 8)
        const float4* W4 = (const float4*)Wc;
        float4* ws4 = (float4*)ws;
#pragma unroll
        for (int i = 0; i < 8; i++) ws4[t + 128 * i] = W4[t + 128 * i];

        // load A tile TRANSPOSED: thread reads float4 along k, scatters 4 floats
#pragma unroll
        for (int i = 0; i < 8; i++) {
            int l = t + 128 * i;
            int r = l >> 4, k4 = l & 15;
            int grow = rowBase + r;
            float4 v = make_float4(0.f, 0.f, 0.f, 0.f);
            if (grow < N_NODES) v = ((const float4*)A)[(size_t)grow * 16 + k4];
            xs[(k4 * 4 + 0) * 66 + r] = v.x;
            xs[(k4 * 4 + 1) * 66 + r] = v.y;
            xs[(k4 * 4 + 2) * 66 + r] = v.z;
            xs[(k4 * 4 + 3) * 66 + r] = v.w;
        }
        __syncthreads();

#pragma unroll 4
        for (int k = 0; k < 64; k++) {
            float4 wv = *(const float4*)&ws[k * 64 + c0];
            u64 w0 = pk2(wv.x, wv.x);
            u64 w1 = pk2(wv.y, wv.y);
            u64 w2 = pk2(wv.z, wv.z);
            u64 w3 = pk2(wv.w, wv.w);
#pragma unroll
            for (int j = 0; j < 4; j++) {
                u64 xp = *(const u64*)&xs[k * 66 + r0 + 2 * j];  // rows pair
                FMA2(acc2[j][0], xp, w0, acc2[j][0]);
                FMA2(acc2[j][1], xp, w1, acc2[j][1]);
                FMA2(acc2[j][2], xp, w2, acc2[j][2]);
                FMA2(acc2[j][3], xp, w3, acc2[j][3]);
            }
        }
        __syncthreads();   // protect xs/ws before next source overwrites
    }

    float* outbuf = buf_sel(out_sel);
    float4 bv = *(const float4*)&bias[c0];
#pragma unroll
    for (int j = 0; j < 4; j++) {
        float lo0, hi0, lo1, hi1, lo2, hi2, lo3, hi3;
        upk2(acc2[j][0], lo0, hi0);
        upk2(acc2[j][1], lo1, hi1);
        upk2(acc2[j][2], lo2, hi2);
        upk2(acc2[j][3], lo3, hi3);
        int grow0 = rowBase + r0 + 2 * j;
        int grow1 = grow0 + 1;
        if (grow0 < N_NODES) {
            float4 v;
            v.x = fmaxf(lo0 + bv.x, 0.f);
            v.y = fmaxf(lo1 + bv.y, 0.f);
            v.z = fmaxf(lo2 + bv.z, 0.f);
            v.w = fmaxf(lo3 + bv.w, 0.f);
            *(float4*)&outbuf[(size_t)grow0 * 64 + c0] = v;
        }
        if (grow1 < N_NODES) {
            float4 v;
            v.x = fmaxf(hi0 + bv.x, 0.f);
            v.y = fmaxf(hi1 + bv.y, 0.f);
            v.z = fmaxf(hi2 + bv.z, 0.f);
            v.w = fmaxf(hi3 + bv.w, 0.f);
            *(float4*)&outbuf[(size_t)grow1 * 64 + c0] = v;
        }
    }
}

// ---------------- readout: segmented mean over sorted graph_ids ----------------
__global__ void k_readout(int in_sel, const int* __restrict__ gid) {
    const float* h = buf_sel(in_sel);
    const int ROWS = 64;
    int w = (blockIdx.x * blockDim.x + threadIdx.x) >> 5;
    int nwarps = (N_NODES + ROWS - 1) / ROWS;
    if (w >= nwarps) return;
    int lane = threadIdx.x & 31;
    int r = w * ROWS;
    int rend = r + ROWS; if (rend > N_NODES) rend = N_NODES;
    int g = gid[r];
    float s0 = 0.f, s1 = 0.f; int cnt = 0;
    for (; r < rend; ++r) {
        int g2 = gid[r];
        if (g2 != g) {
            atomicAdd(&g_gsum[g * HID + lane], s0);
            atomicAdd(&g_gsum[g * HID + 32 + lane], s1);
            if (lane == 0) atomicAdd(&g_gcnt[g], cnt);
            s0 = 0.f; s1 = 0.f; cnt = 0; g = g2;
        }
        s0 += h[(size_t)r * HID + lane];
        s1 += h[(size_t)r * HID + 32 + lane];
        cnt++;
    }
    atomicAdd(&g_gsum[g * HID + lane], s0);
    atomicAdd(&g_gsum[g * HID + 32 + lane], s1);
    if (lane == 0) atomicAdd(&g_gcnt[g], cnt);
}

// ---------------- final: hg = mean; out = normalize(hg @ embW + embb) ----------------
__global__ void k_final(const float* __restrict__ embW, const float* __restrict__ embb,
                        float* __restrict__ out) {
    __shared__ float hg[HID];
    __shared__ float red[EMB];
    int g = blockIdx.x, t = threadIdx.x;  // t: 0..127
    if (t < HID) {
        float c = (float)g_gcnt[g];
        hg[t] = g_gsum[g * HID + t] / fmaxf(c, 1.f);
    }
    __syncthreads();
    float a = embb[t];
#pragma unroll
    for (int i = 0; i < HID; i++) a = fmaf(hg[i], embW[i * EMB + t], a);
    red[t] = a * a;
    __syncthreads();
    for (int s = 64; s > 0; s >>= 1) {
        if (t < s) red[t] += red[t + s];
        __syncthreads();
    }
    float nrm = fmaxf(sqrtf(red[0]), 1e-12f);
    out[g * EMB + t] = a / nrm;
}

// ---------------- launch (pure kernel launches; no runtime API calls) --------
extern "C" void kernel_launch(void* const* d_in, const int* in_sizes, int n_in,
                              void* d_out, int out_size) {
    const float* h     = (const float*)d_in[0];
    const int*   src   = (const int*)  d_in[1];
    const int*   dst   = (const int*)  d_in[2];
    const int*   gid   = (const int*)  d_in[3];
    const float* W0    = (const float*)d_in[4];
    const float* b0    = (const float*)d_in[5];
    const float* W1    = (const float*)d_in[6];
    const float* b1    = (const float*)d_in[7];
    const float* W2    = (const float*)d_in[8];
    const float* b2    = (const float*)d_in[9];
    const float* embW  = (const float*)d_in[10];
    const float* embb  = (const float*)d_in[11];
    float* out = (float*)d_out;

    // build CSR + deg norm
    k_init<<<(N_NODES + 255) / 256, 256>>>();
    k_deg<<<(N_EDGES + 255) / 256, 256>>>(dst);
    k_scan<<<1, 1024>>>();
    k_fill<<<(N_EDGES + 255) / 256, 256>>>(src, dst);

    const int SPMM_BLOCKS = (N_NODES * 32 + 255) / 256;
    const int GEMM_BLOCKS = (N_NODES + 63) / 64;

    const float* Ws[3] = {W0, W1, W2};
    const float* bs[3] = {b0, b1, b2};

    // buffer selectors: 0 = bufA (hop1), 1 = bufB (hop2), 2 = bufC (hop3), 3 = bufD (out)
    int in_sel = -1;                 // layer input: external h for L0, else bufD
    const float* in_ext = h;
    for (int L = 0; L < 3; ++L) {
        k_spmm<<<SPMM_BLOCKS, 256>>>(in_ext, in_sel, 0);     // in -> A
        k_spmm<<<SPMM_BLOCKS, 256>>>(nullptr, 0, 1);         // A  -> B
        k_spmm<<<SPMM_BLOCKS, 256>>>(nullptr, 1, 2);         // B  -> C
        k_gemm4<<<GEMM_BLOCKS, 128>>>(in_ext, in_sel, Ws[L], bs[L], 3);  // -> D
        in_sel = 3; in_ext = nullptr;
    }

    // readout on bufD (sel 3)
    const int RO_WARPS = (N_NODES + 63) / 64;
    k_readout<<<(RO_WARPS * 32 + 255) / 256, 256>>>(3, gid);
    k_final<<<NG, EMB>>>(embW, embb, out);
}

// round 17
// speedup vs baseline: 1.0507x; 1.0507x over previous
#include <cuda_runtime.h>
#include <cuda_bf16.h>
#include <math.h>

#define N_NODES 100000
#define N_EDGES 800000
#define NG 64
#define HID 64
#define EMB 128

typedef unsigned int u32;

// ---------------- device scratch (static allocation only) ----------------
__device__ float g_bufA[N_NODES * HID];   // hop1
__device__ float g_bufB[N_NODES * HID];   // hop2
__device__ float g_bufC[N_NODES * HID];   // hop3
__device__ float g_bufD[N_NODES * HID];   // layer output
__device__ float g_dn  [N_NODES];
__device__ int   g_deg [N_NODES];
__device__ int   g_fill[N_NODES];
__device__ int   g_rowptr[N_NODES + 1];
__device__ int   g_csr[N_EDGES];
__device__ float g_gsum[NG * HID];
__device__ int   g_gcnt[NG];
// W split (bf16 hi/lo), transposed to [layer][n=64][k=256]
__device__ __nv_bfloat16 g_wthi[3 * 64 * 256];
__device__ __nv_bfloat16 g_wtlo[3 * 64 * 256];

__device__ __forceinline__ float* buf_sel(int s) {
    return (s == 0) ? g_bufA : (s == 1) ? g_bufB : (s == 2) ? g_bufC : g_bufD;
}

// ---------------- init / CSR build ----------------
__global__ void k_init() {
    int i = blockIdx.x * blockDim.x + threadIdx.x;
    if (i < N_NODES) { g_deg[i] = 0; g_fill[i] = 0; }
    if (i < NG * HID) g_gsum[i] = 0.f;
    if (i < NG)       g_gcnt[i] = 0;
}

__global__ void k_deg(const int* __restrict__ dst) {
    int e = blockIdx.x * blockDim.x + threadIdx.x;
    if (e < N_EDGES) atomicAdd(&g_deg[dst[e]], 1);
}

// single-block scan (1024 threads) -> rowptr, dn
__global__ void k_scan() {
    __shared__ int sa[1024], sb[1024];
    int t = threadIdx.x;
    const int CH = (N_NODES + 1023) / 1024;   // 98
    int base = t * CH;
    int local = 0;
    for (int i = 0; i < CH; i++) {
        int idx = base + i;
        if (idx < N_NODES) local += g_deg[idx];
    }
    sa[t] = local;
    __syncthreads();
    int* cur = sa; int* nxt = sb;
    for (int off = 1; off < 1024; off <<= 1) {
        int v = cur[t] + ((t >= off) ? cur[t - off] : 0);
        nxt[t] = v;
        __syncthreads();
        int* tmp = cur; cur = nxt; nxt = tmp;
    }
    int excl = cur[t] - local;
    int run = excl;
    for (int i = 0; i < CH; i++) {
        int idx = base + i;
        if (idx < N_NODES) {
            g_rowptr[idx] = run;
            int d = g_deg[idx];
            run += d;
            g_dn[idx] = rsqrtf((float)(d > 1 ? d : 1));
        }
    }
    if (t == 1023) g_rowptr[N_NODES] = run;   // == N_EDGES
}

__global__ void k_fill(const int* __restrict__ src, const int* __restrict__ dst) {
    int e = blockIdx.x * blockDim.x + threadIdx.x;
    if (e < N_EDGES) {
        int d = dst[e];
        int pos = g_rowptr[d] + atomicAdd(&g_fill[d], 1);
        g_csr[pos] = src[e];
    }
}

// ---------------- W split/transpose: wt[L][n][k] = split(W_L[k][n]) ---------
__global__ void k_wsplit(const float* __restrict__ W0, const float* __restrict__ W1,
                         const float* __restrict__ W2) {
    int i = blockIdx.x * blockDim.x + threadIdx.x;
    if (i >= 3 * 64 * 256) return;
    int L = i / (64 * 256);
    int rem = i % (64 * 256);
    int n = rem / 256;
    int k = rem % 256;
    const float* W = (L == 0) ? W0 : (L == 1) ? W1 : W2;
    float f = W[k * 64 + n];
    __nv_bfloat16 hi = __float2bfloat16(f);
    __nv_bfloat16 lo = __float2bfloat16(f - __bfloat162float(hi));
    g_wthi[i] = hi;
    g_wtlo[i] = lo;
}

// ---------------- SpMM: xout[r] = dn[r] * sum_{s in N_in(r)} dn[s]*xin[s] ----
// warp per row; edge loop unrolled x4 for MLP (R5 proven version)
__global__ void __launch_bounds__(256) k_spmm(const float* __restrict__ xin_ext,
                                              int in_sel, int out_sel) {
    const float* xin = (in_sel < 0) ? xin_ext : buf_sel(in_sel);
    float* xout = buf_sel(out_sel);
    int w = (blockIdx.x * blockDim.x + threadIdx.x) >> 5;
    if (w >= N_NODES) return;
    int lane = threadIdx.x & 31;
    int e0 = g_rowptr[w], e1 = g_rowptr[w + 1];
    float a0 = 0.f, a1 = 0.f, b0 = 0.f, b1 = 0.f;
    float c0 = 0.f, c1 = 0.f, d0 = 0.f, d1 = 0.f;
    int e = e0;
    for (; e + 4 <= e1; e += 4) {
        int s0 = g_csr[e], s1 = g_csr[e + 1], s2 = g_csr[e + 2], s3 = g_csr[e + 3];
        float w0 = g_dn[s0], w1 = g_dn[s1], w2 = g_dn[s2], w3 = g_dn[s3];
        float2 v0 = *(const float2*)(xin + (size_t)s0 * HID + lane * 2);
        float2 v1 = *(const float2*)(xin + (size_t)s1 * HID + lane * 2);
        float2 v2 = *(const float2*)(xin + (size_t)s2 * HID + lane * 2);
        float2 v3 = *(const float2*)(xin + (size_t)s3 * HID + lane * 2);
        a0 = fmaf(v0.x, w0, a0); a1 = fmaf(v0.y, w0, a1);
        b0 = fmaf(v1.x, w1, b0); b1 = fmaf(v1.y, w1, b1);
        c0 = fmaf(v2.x, w2, c0); c1 = fmaf(v2.y, w2, c1);
        d0 = fmaf(v3.x, w3, d0); d1 = fmaf(v3.y, w3, d1);
    }
    for (; e < e1; ++e) {
        int s = g_csr[e];
        float wt = g_dn[s];
        float2 v = *(const float2*)(xin + (size_t)s * HID + lane * 2);
        a0 = fmaf(v.x, wt, a0);
        a1 = fmaf(v.y, wt, a1);
    }
    float wd = g_dn[w];
    float2 o;
    o.x = ((a0 + b0) + (c0 + d0)) * wd;
    o.y = ((a1 + b1) + (c1 + d1)) * wd;
    *(float2*)(xout + (size_t)w * HID + lane * 2) = o;
}

// ---------------- tensor-core fused layer GEMM (bf16 split, exact):
//   D = relu( sum_s S_s @ W_s + b ),  S = {in, hop1, hop2, hop3}
// mma.sync.m16n8k16 bf16; A and W split into hi+lo bf16; all 4 cross terms.
__device__ __forceinline__ void mma16816(float* c, u32 a0, u32 a1, u32 a2, u32 a3,
                                         u32 b0, u32 b1) {
    asm volatile(
        "mma.sync.aligned.m16n8k16.row.col.f32.bf16.bf16.f32 "
        "{%0,%1,%2,%3}, {%4,%5,%6,%7}, {%8,%9}, {%0,%1,%2,%3};"
        : "+f"(c[0]), "+f"(c[1]), "+f"(c[2]), "+f"(c[3])
        : "r"(a0), "r"(a1), "r"(a2), "r"(a3), "r"(b0), "r"(b1));
}

#define AS 72   // bf16 stride for 64-wide smem tiles (36 words -> conflict-free frags)

__global__ void __launch_bounds__(128) k_gemm4(const float* __restrict__ in_ext, int in_sel,
                                               int L,
                                               const float* __restrict__ bias,
                                               int out_sel) {
    __shared__ __nv_bfloat16 a_hi[64 * AS];
    __shared__ __nv_bfloat16 a_lo[64 * AS];
    __shared__ __nv_bfloat16 w_hi[64 * AS];   // [n][k] for current source
    __shared__ __nv_bfloat16 w_lo[64 * AS];

    int t = threadIdx.x;
    int rowBase = blockIdx.x * 64;
    int wid = t >> 5, lane = t & 31;
    int gr = lane >> 2, tg = lane & 3;
    int warpRow = wid * 16;

    float acc[8][4];
#pragma unroll
    for (int nt = 0; nt < 8; nt++)
#pragma unroll
        for (int c = 0; c < 4; c++) acc[nt][c] = 0.f;

    const float* in0 = (in_sel < 0) ? in_ext : buf_sel(in_sel);

    for (int s = 0; s < 4; ++s) {
        const float* A = (s == 0) ? in0 : buf_sel(s - 1);

        // --- load A tile (64x64 fp32), convert to hi/lo bf16 smem ---
#pragma unroll
        for (int i = 0; i < 8; i++) {
            int l = t + 128 * i;
            int r = l >> 4, k4 = l & 15;
            int grow = rowBase + r;
            float4 v = make_float4(0.f, 0.f, 0.f, 0.f);
            if (grow < N_NODES) v = ((const float4*)A)[(size_t)grow * 16 + k4];
            __nv_bfloat16 h0 = __float2bfloat16(v.x);
            __nv_bfloat16 h1 = __float2bfloat16(v.y);
            __nv_bfloat16 h2 = __float2bfloat16(v.z);
            __nv_bfloat16 h3 = __float2bfloat16(v.w);
            __nv_bfloat16 l0 = __float2bfloat16(v.x - __bfloat162float(h0));
            __nv_bfloat16 l1 = __float2bfloat16(v.y - __bfloat162float(h1));
            __nv_bfloat16 l2 = __float2bfloat16(v.z - __bfloat162float(h2));
            __nv_bfloat16 l3 = __float2bfloat16(v.w - __bfloat162float(h3));
            int o = r * AS + k4 * 4;
            a_hi[o] = h0; a_hi[o + 1] = h1; a_hi[o + 2] = h2; a_hi[o + 3] = h3;
            a_lo[o] = l0; a_lo[o + 1] = l1; a_lo[o + 2] = l2; a_lo[o + 3] = l3;
        }

        // --- copy W chunk [n=64][k=s*64..s*64+64) hi/lo into smem ---
        {
            int n = t >> 1, hf = t & 1;     // thread covers 32 bf16 of row n
            const __nv_bfloat16* srcH = &g_wthi[((L * 64) + n) * 256 + s * 64 + hf * 32];
            const __nv_bfloat16* srcL = &g_wtlo[((L * 64) + n) * 256 + s * 64 + hf * 32];
#pragma unroll
            for (int j = 0; j < 4; j++) {
                *(uint4*)&w_hi[n * AS + hf * 32 + j * 8] = *(const uint4*)&srcH[j * 8];
                *(uint4*)&w_lo[n * AS + hf * 32 + j * 8] = *(const uint4*)&srcL[j * 8];
            }
        }
        __syncthreads();

        // --- MMA over 4 k-tiles x 8 n-tiles ---
#pragma unroll
        for (int kt = 0; kt < 4; kt++) {
            int k0 = kt * 16;
            int ra = (warpRow + gr) * AS + k0 + 2 * tg;
            u32 ah0 = *(const u32*)&a_hi[ra];
            u32 ah1 = *(const u32*)&a_hi[ra + 8 * AS];
            u32 ah2 = *(const u32*)&a_hi[ra + 8];
            u32 ah3 = *(const u32*)&a_hi[ra + 8 * AS + 8];
            u32 al0 = *(const u32*)&a_lo[ra];
            u32 al1 = *(const u32*)&a_lo[ra + 8 * AS];
            u32 al2 = *(const u32*)&a_lo[ra + 8];
            u32 al3 = *(const u32*)&a_lo[ra + 8 * AS + 8];
#pragma unroll
            for (int nt = 0; nt < 8; nt++) {
                int rb = (nt * 8 + gr) * AS + k0 + 2 * tg;
                u32 bh0 = *(const u32*)&w_hi[rb];
                u32 bh1 = *(const u32*)&w_hi[rb + 8];
                u32 bl0 = *(const u32*)&w_lo[rb];
                u32 bl1 = *(const u32*)&w_lo[rb + 8];
                mma16816(acc[nt], ah0, ah1, ah2, ah3, bh0, bh1);   // hi*hi
                mma16816(acc[nt], ah0, ah1, ah2, ah3, bl0, bl1);   // hi*lo
                mma16816(acc[nt], al0, al1, al2, al3, bh0, bh1);   // lo*hi
                mma16816(acc[nt], al0, al1, al2, al3, bl0, bl1);   // lo*lo
            }
        }
        __syncthreads();   // protect smem before next source overwrites
    }

    // --- epilogue: bias + relu, write D ---
    float* outbuf = buf_sel(out_sel);
    int row0 = rowBase + warpRow + gr;
    int row1 = row0 + 8;
#pragma unroll
    for (int nt = 0; nt < 8; nt++) {
        int col = nt * 8 + 2 * tg;
        float bx = bias[col], by = bias[col + 1];
        if (row0 < N_NODES) {
            float2 v;
            v.x = fmaxf(acc[nt][0] + bx, 0.f);
            v.y = fmaxf(acc[nt][1] + by, 0.f);
            *(float2*)&outbuf[(size_t)row0 * 64 + col] = v;
        }
        if (row1 < N_NODES) {
            float2 v;
            v.x = fmaxf(acc[nt][2] + bx, 0.f);
            v.y = fmaxf(acc[nt][3] + by, 0.f);
            *(float2*)&outbuf[(size_t)row1 * 64 + col] = v;
        }
    }
}

// ---------------- readout: segmented mean over sorted graph_ids ----------------
__global__ void k_readout(int in_sel, const int* __restrict__ gid) {
    const float* h = buf_sel(in_sel);
    const int ROWS = 64;
    int w = (blockIdx.x * blockDim.x + threadIdx.x) >> 5;
    int nwarps = (N_NODES + ROWS - 1) / ROWS;
    if (w >= nwarps) return;
    int lane = threadIdx.x & 31;
    int r = w * ROWS;
    int rend = r + ROWS; if (rend > N_NODES) rend = N_NODES;
    int g = gid[r];
    float s0 = 0.f, s1 = 0.f; int cnt = 0;
    for (; r < rend; ++r) {
        int g2 = gid[r];
        if (g2 != g) {
            atomicAdd(&g_gsum[g * HID + lane], s0);
            atomicAdd(&g_gsum[g * HID + 32 + lane], s1);
            if (lane == 0) atomicAdd(&g_gcnt[g], cnt);
            s0 = 0.f; s1 = 0.f; cnt = 0; g = g2;
        }
        s0 += h[(size_t)r * HID + lane];
        s1 += h[(size_t)r * HID + 32 + lane];
        cnt++;
    }
    atomicAdd(&g_gsum[g * HID + lane], s0);
    atomicAdd(&g_gsum[g * HID + 32 + lane], s1);
    if (lane == 0) atomicAdd(&g_gcnt[g], cnt);
}

// ---------------- final: hg = mean; out = normalize(hg @ embW + embb) ----------------
__global__ void k_final(const float* __restrict__ embW, const float* __restrict__ embb,
                        float* __restrict__ out) {
    __shared__ float hg[HID];
    __shared__ float red[EMB];
    int g = blockIdx.x, t = threadIdx.x;  // t: 0..127
    if (t < HID) {
        float c = (float)g_gcnt[g];
        hg[t] = g_gsum[g * HID + t] / fmaxf(c, 1.f);
    }
    __syncthreads();
    float a = embb[t];
#pragma unroll
    for (int i = 0; i < HID; i++) a = fmaf(hg[i], embW[i * EMB + t], a);
    red[t] = a * a;
    __syncthreads();
    for (int s = 64; s > 0; s >>= 1) {
        if (t < s) red[t] += red[t + s];
        __syncthreads();
    }
    float nrm = fmaxf(sqrtf(red[0]), 1e-12f);
    out[g * EMB + t] = a / nrm;
}

// ---------------- launch (pure kernel launches; no runtime API calls) --------
extern "C" void kernel_launch(void* const* d_in, const int* in_sizes, int n_in,
                              void* d_out, int out_size) {
    const float* h     = (const float*)d_in[0];
    const int*   src   = (const int*)  d_in[1];
    const int*   dst   = (const int*)  d_in[2];
    const int*   gid   = (const int*)  d_in[3];
    const float* W0    = (const float*)d_in[4];
    const float* b0    = (const float*)d_in[5];
    const float* W1    = (const float*)d_in[6];
    const float* b1    = (const float*)d_in[7];
    const float* W2    = (const float*)d_in[8];
    const float* b2    = (const float*)d_in[9];
    const float* embW  = (const float*)d_in[10];
    const float* embb  = (const float*)d_in[11];
    float* out = (float*)d_out;

    // build CSR + deg norm ; split W for tensor cores
    k_init<<<(N_NODES + 255) / 256, 256>>>();
    k_deg<<<(N_EDGES + 255) / 256, 256>>>(dst);
    k_wsplit<<<(3 * 64 * 256 + 255) / 256, 256>>>(W0, W1, W2);
    k_scan<<<1, 1024>>>();
    k_fill<<<(N_EDGES + 255) / 256, 256>>>(src, dst);

    const int SPMM_BLOCKS = (N_NODES * 32 + 255) / 256;
    const int GEMM_BLOCKS = (N_NODES + 63) / 64;

    const float* bs[3] = {b0, b1, b2};

    // buffer selectors: 0 = bufA (hop1), 1 = bufB (hop2), 2 = bufC (hop3), 3 = bufD
    int in_sel = -1;
    const float* in_ext = h;
    for (int L = 0; L < 3; ++L) {
        k_spmm<<<SPMM_BLOCKS, 256>>>(in_ext, in_sel, 0);     // in -> A
        k_spmm<<<SPMM_BLOCKS, 256>>>(nullptr, 0, 1);         // A  -> B
        k_spmm<<<SPMM_BLOCKS, 256>>>(nullptr, 1, 2);         // B  -> C
        k_gemm4<<<GEMM_BLOCKS, 128>>>(in_ext, in_sel, L, bs[L], 3);  // -> D
        in_sel = 3; in_ext = nullptr;
    }

    // readout on bufD (sel 3)
    const int RO_WARPS = (N_NODES + 63) / 64;
    k_readout<<<(RO_WARPS * 32 + 255) / 256, 256>>>(3, gid);
    k_final<<<NG, EMB>>>(embW, embb, out);
}